// round 7
// baseline (speedup 1.0000x reference)
#include <cuda_runtime.h>
#include <cstdint>

// Shapes (fixed): B=8, S=4096, E=512 -> M=32768, N=K=512
#define M_TOT 32768
#define N_TOT 512
#define K_TOT 512

#define BM 128
#define BN 256
#define BK 32
#define NTH 256
#define NCH (K_TOT / BK)          // 16
#define NSTAGE 4

// smem per stage: A[128][36] + B[256][36] floats (pad 4: conflict-free frag loads)
#define ROWF 36
#define B_OFF (128 * ROWF)                  // floats, A tile first
#define STG_F (128 * ROWF + 256 * ROWF)     // 13824 floats / stage
#define SMEM_BYTES (NSTAGE * STG_F * 4)     // 221184 B -> 1 CTA/SM

// ---------------- scratch (device globals: sanctioned no-alloc path) ----------
__device__ float g_V [(size_t)M_TOT * N_TOT];
__device__ float g_Vc[(size_t)M_TOT * N_TOT];
__device__ float g_Wa[(size_t)N_TOT * K_TOT];   // pre-rounded input_weights
__device__ float g_Wb[(size_t)N_TOT * K_TOT];   // pre-rounded out_proj_w

__device__ __forceinline__ uint32_t f2tf(float x) {
    uint32_t u;
    asm("cvt.rna.tf32.f32 %0, %1;" : "=r"(u) : "f"(x));
    return u;
}
__device__ __forceinline__ uint32_t smem_u32(const void* p) {
    uint32_t a;
    asm("{ .reg .u64 t; cvta.to.shared.u64 t, %1; cvt.u32.u64 %0, t; }" : "=r"(a) : "l"(p));
    return a;
}
__device__ __forceinline__ void cp16(uint32_t saddr, const void* gptr) {
    asm volatile("cp.async.cg.shared.global [%0], [%1], 16;"
                 :: "r"(saddr), "l"(gptr) : "memory");
}
__device__ __forceinline__ void mma8(float* c, const uint32_t* a,
                                     uint32_t b0, uint32_t b1) {
    asm volatile(
        "mma.sync.aligned.m16n8k8.row.col.f32.tf32.tf32.f32 "
        "{%0,%1,%2,%3}, {%4,%5,%6,%7}, {%8,%9}, {%0,%1,%2,%3};"
        : "+f"(c[0]), "+f"(c[1]), "+f"(c[2]), "+f"(c[3])
        : "r"(a[0]), "r"(a[1]), "r"(a[2]), "r"(a[3]), "r"(b0), "r"(b1));
}

// C[m,n] = sum_k A[m,k]*B[n,k]; A:[M,K] f32 row-major, B:[N,K] tf32-prerounded.
// Warp tile 64x64: 8 warps as 2(m) x 4(n).
template <bool ROUND_A>
__global__ __launch_bounds__(NTH, 1)
void gemm_cp3(const float* __restrict__ A,
              const float* __restrict__ B,
              float* __restrict__ C)
{
    extern __shared__ float sm[];
    const uint32_t sb = smem_u32(sm);
    const int tid  = threadIdx.x;
    const int wid  = tid >> 5;
    const int lane = tid & 31;
    const int wm   = wid >> 2;     // 0..1 -> 64-row stripe
    const int wn   = wid & 3;      // 0..3 -> 64-col stripe
    const int lr   = lane >> 2;
    const int lc   = lane & 3;
    const int bm   = blockIdx.y * BM;
    const int bn   = blockIdx.x * BN;

    const float4* Ag = (const float4*)(A + (size_t)bm * K_TOT);
    const float4* Bg = (const float4*)(B + (size_t)bn * K_TOT);

    auto issue = [&](int c, int s) {
        const uint32_t sa  = sb + (uint32_t)(s * STG_F) * 4u;
        const uint32_t sbB = sa + (uint32_t)B_OFF * 4u;
        #pragma unroll
        for (int i = 0; i < 4; i++) {                // A: 128 rows x 8 f4
            int f = tid + i * NTH, m = f >> 3, q = f & 7;
            cp16(sa + (uint32_t)(m * ROWF + q * 4) * 4u,
                 Ag + (size_t)m * (K_TOT / 4) + c * 8 + q);
        }
        #pragma unroll
        for (int i = 0; i < 8; i++) {                // B: 256 rows x 8 f4
            int f = tid + i * NTH, n = f >> 3, q = f & 7;
            cp16(sbB + (uint32_t)(n * ROWF + q * 4) * 4u,
                 Bg + (size_t)n * (K_TOT / 4) + c * 8 + q);
        }
        asm volatile("cp.async.commit_group;" ::: "memory");
    };

    float acc[4][8][4];
    #pragma unroll
    for (int a = 0; a < 4; a++)
        #pragma unroll
        for (int b = 0; b < 8; b++)
            #pragma unroll
            for (int r = 0; r < 4; r++) acc[a][b][r] = 0.0f;

    issue(0, 0);
    issue(1, 1);
    issue(2, 2);

    for (int c = 0; c < NCH; c++) {
        asm volatile("cp.async.wait_group 2;" ::: "memory");
        __syncthreads();
        if (c + 3 < NCH) issue(c + 3, (c + 3) % NSTAGE);
        else asm volatile("cp.async.commit_group;" ::: "memory");

        const float* As = sm + (c % NSTAGE) * STG_F;
        const float* Bs = As + B_OFF;

        #pragma unroll
        for (int ks = 0; ks < 4; ks++) {
            const int kb = ks * 8;
            uint32_t a[4][4], b[8][2];
            #pragma unroll
            for (int mt = 0; mt < 4; mt++) {
                const float* ap = As + (wm * 64 + mt * 16 + lr) * ROWF + kb + lc;
                float a0 = ap[0], a1 = ap[8 * ROWF], a2 = ap[4], a3 = ap[8 * ROWF + 4];
                if (ROUND_A) {
                    a[mt][0] = f2tf(a0); a[mt][1] = f2tf(a1);
                    a[mt][2] = f2tf(a2); a[mt][3] = f2tf(a3);
                } else {
                    a[mt][0] = __float_as_uint(a0); a[mt][1] = __float_as_uint(a1);
                    a[mt][2] = __float_as_uint(a2); a[mt][3] = __float_as_uint(a3);
                }
            }
            #pragma unroll
            for (int nt = 0; nt < 8; nt++) {
                const float* bp = Bs + (wn * 64 + nt * 8 + lr) * ROWF + kb + lc;
                b[nt][0] = __float_as_uint(bp[0]);
                b[nt][1] = __float_as_uint(bp[4]);
            }
            #pragma unroll
            for (int mt = 0; mt < 4; mt++)
                #pragma unroll
                for (int nt = 0; nt < 8; nt++)
                    mma8(acc[mt][nt], a[mt], b[nt][0], b[nt][1]);
        }
    }

    // ---- epilogue ----
    #pragma unroll
    for (int mt = 0; mt < 4; mt++) {
        int m = bm + wm * 64 + mt * 16 + lr;
        float* crow = C + (size_t)m * N_TOT + bn + wn * 64;
        #pragma unroll
        for (int nt = 0; nt < 8; nt++) {
            int nf = nt * 8 + lc * 2;
            *(float2*)(crow + nf) = make_float2(acc[mt][nt][0], acc[mt][nt][1]);
            *(float2*)(crow + nf + (size_t)8 * N_TOT) =
                make_float2(acc[mt][nt][2], acc[mt][nt][3]);
        }
    }
}

// ---------------- weight pre-round to tf32 (rna) ----------------
__global__ void round_w_kernel(const float4* __restrict__ w, float4* __restrict__ o)
{
    int i = blockIdx.x * 256 + threadIdx.x;      // 65536 float4
    float4 v = w[i];
    o[i] = make_float4(__uint_as_float(f2tf(v.x)), __uint_as_float(f2tf(v.y)),
                       __uint_as_float(f2tf(v.z)), __uint_as_float(f2tf(v.w)));
}

// ---- 5-tap Gaussian window, per-head shift {0,-1,+1,0}x2; output tf32-rounded
__global__ void conv_kernel(const float4* __restrict__ V, float4* __restrict__ Vc)
{
    int idx = blockIdx.x * blockDim.x + threadIdx.x;   // M_TOT*128 threads
    int c4  = idx & 127;
    int m   = idx >> 7;
    int s   = m & 4095;
    int mb0 = m - s;
    int hm  = (c4 >> 4) & 3;
    int shift = (hm == 1) ? -1 : ((hm == 2) ? 1 : 0);

    const float F[5] = {0.05399096651318806f, 0.24197072451914337f,
                        0.3989422804014327f,  0.24197072451914337f,
                        0.05399096651318806f};

    float ax = 0.f, ay = 0.f, az = 0.f, aw = 0.f;
    #pragma unroll
    for (int j = 0; j < 5; j++) {
        int ss = s + shift + j - 2;
        if (ss >= 0 && ss < 4096) {
            float4 v = V[(size_t)(mb0 + ss) * 128 + c4];
            ax += F[j] * v.x; ay += F[j] * v.y; az += F[j] * v.z; aw += F[j] * v.w;
        }
    }
    Vc[idx] = make_float4(__uint_as_float(f2tf(ax)), __uint_as_float(f2tf(ay)),
                          __uint_as_float(f2tf(az)), __uint_as_float(f2tf(aw)));
}

// ---------------- launcher ----------------
extern "C" void kernel_launch(void* const* d_in, const int* in_sizes, int n_in,
                              void* d_out, int out_size)
{
    const float* values = (const float*)d_in[0];
    const float* win    = (const float*)d_in[3];
    const float* wout   = (const float*)d_in[4];
    float*       out    = (float*)d_out;

    float *pV, *pVc, *pWa, *pWb;
    cudaGetSymbolAddress((void**)&pV,  g_V);
    cudaGetSymbolAddress((void**)&pVc, g_Vc);
    cudaGetSymbolAddress((void**)&pWa, g_Wa);
    cudaGetSymbolAddress((void**)&pWb, g_Wb);

    cudaFuncSetAttribute(gemm_cp3<true>,
                         cudaFuncAttributeMaxDynamicSharedMemorySize, SMEM_BYTES);
    cudaFuncSetAttribute(gemm_cp3<false>,
                         cudaFuncAttributeMaxDynamicSharedMemorySize, SMEM_BYTES);

    dim3 grid(N_TOT / BN, M_TOT / BM);   // (2, 256)

    round_w_kernel<<<256, 256>>>((const float4*)win,  (float4*)pWa);
    round_w_kernel<<<256, 256>>>((const float4*)wout, (float4*)pWb);
    gemm_cp3<true ><<<grid, NTH, SMEM_BYTES>>>(values, pWa, pV);
    conv_kernel<<<(M_TOT * 128) / 256, 256>>>((const float4*)pV, (float4*)pVc);
    gemm_cp3<false><<<grid, NTH, SMEM_BYTES>>>(pVc, pWb, out);
}

// round 8
// speedup vs baseline: 1.1048x; 1.1048x over previous
#include <cuda_runtime.h>
#include <cstdint>

// Shapes (fixed): B=8, S=4096, E=512 -> M=32768, N=K=512
#define M_TOT 32768
#define N_TOT 512
#define K_TOT 512

#define BM 128
#define BN 128
#define BK 32
#define NTH 256
#define NCH (K_TOT / BK)          // 16
#define NSTAGE 3

// smem: per stage A[128][36] + B[128][36] floats (pad 4 -> conflict-free LDSM)
#define ROWF 36
#define B_OFF (128 * ROWF)        // floats
#define STG_F (2 * 128 * ROWF)    // 9216 floats / stage
#define SMEM_BYTES (NSTAGE * STG_F * 4)   // 110592 B -> 2 CTAs/SM

// ---------------- scratch (device globals: sanctioned no-alloc path) ----------
__device__ float g_V [(size_t)M_TOT * N_TOT];
__device__ float g_Vc[(size_t)M_TOT * N_TOT];
__device__ float g_Va[(size_t)M_TOT * K_TOT];   // pre-rounded values
__device__ float g_Wa[(size_t)N_TOT * K_TOT];   // pre-rounded input_weights
__device__ float g_Wb[(size_t)N_TOT * K_TOT];   // pre-rounded out_proj_w

__device__ __forceinline__ uint32_t f2tf(float x) {
    uint32_t u;
    asm("cvt.rna.tf32.f32 %0, %1;" : "=r"(u) : "f"(x));
    return u;
}
__device__ __forceinline__ uint32_t smem_u32(const void* p) {
    uint32_t a;
    asm("{ .reg .u64 t; cvta.to.shared.u64 t, %1; cvt.u32.u64 %0, t; }" : "=r"(a) : "l"(p));
    return a;
}
__device__ __forceinline__ void cp16(uint32_t saddr, const void* gptr) {
    asm volatile("cp.async.cg.shared.global [%0], [%1], 16;"
                 :: "r"(saddr), "l"(gptr) : "memory");
}
// ldmatrix x4 on 8x4-float tiles (viewed as 8x8 b16): delivers tf32 fragments.
__device__ __forceinline__ void ldsm4(uint32_t* r, uint32_t addr) {
    asm volatile("ldmatrix.sync.aligned.m8n8.x4.shared.b16 {%0,%1,%2,%3}, [%4];"
                 : "=r"(r[0]), "=r"(r[1]), "=r"(r[2]), "=r"(r[3]) : "r"(addr));
}
__device__ __forceinline__ void mma8(float* c, const uint32_t* a,
                                     uint32_t b0, uint32_t b1) {
    asm volatile(
        "mma.sync.aligned.m16n8k8.row.col.f32.tf32.tf32.f32 "
        "{%0,%1,%2,%3}, {%4,%5,%6,%7}, {%8,%9}, {%0,%1,%2,%3};"
        : "+f"(c[0]), "+f"(c[1]), "+f"(c[2]), "+f"(c[3])
        : "r"(a[0]), "r"(a[1]), "r"(a[2]), "r"(a[3]), "r"(b0), "r"(b1));
}

// C[m,n] = sum_k A[m,k]*B[n,k]; A,B already tf32-rounded fp32, row-major [.,K].
__global__ __launch_bounds__(NTH, 2)
void gemm_lds(const float* __restrict__ A,
              const float* __restrict__ B,
              float* __restrict__ C)
{
    extern __shared__ float sm[];
    const uint32_t sb = smem_u32(sm);
    const int tid  = threadIdx.x;
    const int wid  = tid >> 5;
    const int lane = tid & 31;
    const int wm   = wid >> 2;     // 0..1 -> 64-row stripe
    const int wn   = wid & 3;      // 0..3 -> 32-col stripe
    const int lr   = lane >> 2;
    const int lc   = lane & 3;
    const int bm   = blockIdx.y * BM;
    const int bn   = blockIdx.x * BN;

    const float4* Ag = (const float4*)(A + (size_t)bm * K_TOT);
    const float4* Bg = (const float4*)(B + (size_t)bn * K_TOT);

    // per-lane LDSM byte offsets (groups of 8 lanes -> one 8x4-float matrix)
    // A call (per mt): g0 rows r @k, g1 rows r+8 @k, g2 rows r @k+4, g3 rows r+8 @k+4
    const uint32_t laneA = ((((lane >> 3) & 1) * 8 + (lane & 7)) * ROWF
                            + ((lane >> 4) * 4)) * 4u;
    // B call (per pair p): g0 n+r @k, g1 n+r @k+4, g2 n+8+r @k, g3 n+8+r @k+4
    const uint32_t laneB = (((lane >> 4) * 8 + (lane & 7)) * ROWF
                            + (((lane >> 3) & 1) * 4)) * 4u;

    auto issue = [&](int c, int s) {
        const uint32_t sa  = sb + (uint32_t)(s * STG_F) * 4u;
        const uint32_t sbB = sa + (uint32_t)B_OFF * 4u;
        #pragma unroll
        for (int i = 0; i < 4; i++) {
            int f = tid + i * NTH, m = f >> 3, q = f & 7;
            cp16(sa + (uint32_t)(m * ROWF + q * 4) * 4u,
                 Ag + (size_t)m * (K_TOT / 4) + c * 8 + q);
        }
        #pragma unroll
        for (int i = 0; i < 4; i++) {
            int f = tid + i * NTH, n = f >> 3, q = f & 7;
            cp16(sbB + (uint32_t)(n * ROWF + q * 4) * 4u,
                 Bg + (size_t)n * (K_TOT / 4) + c * 8 + q);
        }
        asm volatile("cp.async.commit_group;" ::: "memory");
    };

    float acc[4][4][4];
    #pragma unroll
    for (int a = 0; a < 4; a++)
        #pragma unroll
        for (int b = 0; b < 4; b++)
            #pragma unroll
            for (int r = 0; r < 4; r++) acc[a][b][r] = 0.0f;

    issue(0, 0);
    issue(1, 1);

    for (int c = 0; c < NCH; c++) {
        asm volatile("cp.async.wait_group 1;" ::: "memory");
        __syncthreads();
        if (c + 2 < NCH) issue(c + 2, (c + 2) % NSTAGE);
        else asm volatile("cp.async.commit_group;" ::: "memory");

        const uint32_t sA = sb + (uint32_t)((c % NSTAGE) * STG_F) * 4u;
        const uint32_t sB = sA + (uint32_t)B_OFF * 4u;
        const uint32_t aBase = sA + (uint32_t)(wm * 64 * ROWF) * 4u + laneA;
        const uint32_t bBase = sB + (uint32_t)(wn * 32 * ROWF) * 4u + laneB;

        #pragma unroll
        for (int ks = 0; ks < 4; ks++) {
            const uint32_t kbb = (uint32_t)ks * 32u;   // k offset in bytes
            uint32_t a[4][4], b[2][4];
            #pragma unroll
            for (int mt = 0; mt < 4; mt++)
                ldsm4(a[mt], aBase + (uint32_t)(mt * 16 * ROWF) * 4u + kbb);
            #pragma unroll
            for (int p = 0; p < 2; p++)
                ldsm4(b[p], bBase + (uint32_t)(p * 16 * ROWF) * 4u + kbb);
            #pragma unroll
            for (int mt = 0; mt < 4; mt++) {
                #pragma unroll
                for (int nt = 0; nt < 4; nt++) {
                    // b[p] regs: {b[2p][0], b[2p][1], b[2p+1][0], b[2p+1][1]}
                    uint32_t b0 = b[nt >> 1][(nt & 1) * 2 + 0];
                    uint32_t b1 = b[nt >> 1][(nt & 1) * 2 + 1];
                    mma8(acc[mt][nt], a[mt], b0, b1);
                }
            }
        }
    }

    // ---- epilogue ----
    #pragma unroll
    for (int mt = 0; mt < 4; mt++) {
        int m = bm + wm * 64 + mt * 16 + lr;
        float* crow = C + (size_t)m * N_TOT + bn + wn * 32;
        #pragma unroll
        for (int nt = 0; nt < 4; nt++) {
            int nf = nt * 8 + lc * 2;
            *(float2*)(crow + nf) = make_float2(acc[mt][nt][0], acc[mt][nt][1]);
            *(float2*)(crow + nf + (size_t)8 * N_TOT) =
                make_float2(acc[mt][nt][2], acc[mt][nt][3]);
        }
    }
}

// ---------------- tf32 (rna) pre-round, vectorized ----------------
__global__ void round_kernel(const float4* __restrict__ w, float4* __restrict__ o)
{
    int i = blockIdx.x * 256 + threadIdx.x;
    float4 v = w[i];
    o[i] = make_float4(__uint_as_float(f2tf(v.x)), __uint_as_float(f2tf(v.y)),
                       __uint_as_float(f2tf(v.z)), __uint_as_float(f2tf(v.w)));
}

// ---- 5-tap Gaussian window, per-head shift {0,-1,+1,0}x2; output tf32-rounded
__global__ void conv_kernel(const float4* __restrict__ V, float4* __restrict__ Vc)
{
    int idx = blockIdx.x * blockDim.x + threadIdx.x;   // M_TOT*128 threads
    int c4  = idx & 127;
    int m   = idx >> 7;
    int s   = m & 4095;
    int mb0 = m - s;
    int hm  = (c4 >> 4) & 3;
    int shift = (hm == 1) ? -1 : ((hm == 2) ? 1 : 0);

    const float F[5] = {0.05399096651318806f, 0.24197072451914337f,
                        0.3989422804014327f,  0.24197072451914337f,
                        0.05399096651318806f};

    float ax = 0.f, ay = 0.f, az = 0.f, aw = 0.f;
    #pragma unroll
    for (int j = 0; j < 5; j++) {
        int ss = s + shift + j - 2;
        if (ss >= 0 && ss < 4096) {
            float4 v = V[(size_t)(mb0 + ss) * 128 + c4];
            ax += F[j] * v.x; ay += F[j] * v.y; az += F[j] * v.z; aw += F[j] * v.w;
        }
    }
    Vc[idx] = make_float4(__uint_as_float(f2tf(ax)), __uint_as_float(f2tf(ay)),
                          __uint_as_float(f2tf(az)), __uint_as_float(f2tf(aw)));
}

// ---------------- launcher ----------------
extern "C" void kernel_launch(void* const* d_in, const int* in_sizes, int n_in,
                              void* d_out, int out_size)
{
    const float* values = (const float*)d_in[0];
    const float* win    = (const float*)d_in[3];
    const float* wout   = (const float*)d_in[4];
    float*       out    = (float*)d_out;

    float *pV, *pVc, *pVa, *pWa, *pWb;
    cudaGetSymbolAddress((void**)&pV,  g_V);
    cudaGetSymbolAddress((void**)&pVc, g_Vc);
    cudaGetSymbolAddress((void**)&pVa, g_Va);
    cudaGetSymbolAddress((void**)&pWa, g_Wa);
    cudaGetSymbolAddress((void**)&pWb, g_Wb);

    cudaFuncSetAttribute(gemm_lds,
                         cudaFuncAttributeMaxDynamicSharedMemorySize, SMEM_BYTES);

    dim3 grid(N_TOT / BN, M_TOT / BM);   // (4, 256)

    round_kernel<<<256, 256>>>((const float4*)win,  (float4*)pWa);
    round_kernel<<<256, 256>>>((const float4*)wout, (float4*)pWb);
    round_kernel<<<(M_TOT * K_TOT / 4) / 256, 256>>>((const float4*)values,
                                                     (float4*)pVa);
    gemm_lds<<<grid, NTH, SMEM_BYTES>>>(pVa, pWa, pV);
    conv_kernel<<<(M_TOT * 128) / 256, 256>>>((const float4*)pV, (float4*)pVc);
    gemm_lds<<<grid, NTH, SMEM_BYTES>>>(pVc, pWb, out);
}

// round 9
// speedup vs baseline: 1.1439x; 1.0354x over previous
#include <cuda_runtime.h>
#include <cstdint>

// Shapes (fixed): B=8, S=4096, E=512 -> M=32768, N=K=512
#define M_TOT 32768
#define N_TOT 512
#define K_TOT 512

#define BM 128
#define BN 128
#define BK 32
#define NTH 256
#define NCH (K_TOT / BK)          // 16
#define NSTAGE 3

// smem: per stage A[128][36] + B[128][36] floats (pad 4 -> conflict-free LDSM)
#define ROWF 36
#define B_OFF (128 * ROWF)        // floats
#define STG_F (2 * 128 * ROWF)    // 9216 floats / stage
#define SMEM_BYTES (NSTAGE * STG_F * 4)   // 110592 B -> 2 CTAs/SM

// ---------------- scratch (device globals: sanctioned no-alloc path) ----------
__device__ float g_V [(size_t)M_TOT * N_TOT];
__device__ float g_Vc[(size_t)M_TOT * N_TOT];
__device__ float g_Wa[(size_t)N_TOT * K_TOT];   // pre-rounded input_weights
__device__ float g_Wb[(size_t)N_TOT * K_TOT];   // pre-rounded out_proj_w

__device__ __forceinline__ uint32_t f2tf(float x) {
    uint32_t u;
    asm("cvt.rna.tf32.f32 %0, %1;" : "=r"(u) : "f"(x));
    return u;
}
__device__ __forceinline__ uint32_t smem_u32(const void* p) {
    uint32_t a;
    asm("{ .reg .u64 t; cvta.to.shared.u64 t, %1; cvt.u32.u64 %0, t; }" : "=r"(a) : "l"(p));
    return a;
}
__device__ __forceinline__ void cp16(uint32_t saddr, const void* gptr) {
    asm volatile("cp.async.cg.shared.global [%0], [%1], 16;"
                 :: "r"(saddr), "l"(gptr) : "memory");
}
// ldmatrix x4 on 8x4-float tiles (viewed as 8x8 b16): delivers tf32 fragments.
__device__ __forceinline__ void ldsm4(uint32_t* r, uint32_t addr) {
    asm volatile("ldmatrix.sync.aligned.m8n8.x4.shared.b16 {%0,%1,%2,%3}, [%4];"
                 : "=r"(r[0]), "=r"(r[1]), "=r"(r[2]), "=r"(r[3]) : "r"(addr));
}
__device__ __forceinline__ void mma8(float* c, const uint32_t* a,
                                     uint32_t b0, uint32_t b1) {
    asm volatile(
        "mma.sync.aligned.m16n8k8.row.col.f32.tf32.tf32.f32 "
        "{%0,%1,%2,%3}, {%4,%5,%6,%7}, {%8,%9}, {%0,%1,%2,%3};"
        : "+f"(c[0]), "+f"(c[1]), "+f"(c[2]), "+f"(c[3])
        : "r"(a[0]), "r"(a[1]), "r"(a[2]), "r"(a[3]), "r"(b0), "r"(b1));
}

// C[m,n] = sum_k A[m,k]*B[n,k]; B tf32-prerounded; ROUND_A rounds A fragments.
// Warp k-slice order staggered by warp id to overlap LDSM (shared port) with
// HMMA (tensor pipe) across warps instead of phase-aligning them.
template <bool ROUND_A>
__global__ __launch_bounds__(NTH, 2)
void gemm_lds(const float* __restrict__ A,
              const float* __restrict__ B,
              float* __restrict__ C)
{
    extern __shared__ float sm[];
    const uint32_t sb = smem_u32(sm);
    const int tid  = threadIdx.x;
    const int wid  = tid >> 5;
    const int lane = tid & 31;
    const int wm   = wid >> 2;     // 0..1 -> 64-row stripe
    const int wn   = wid & 3;      // 0..3 -> 32-col stripe
    const int lr   = lane >> 2;
    const int lc   = lane & 3;
    const int bm   = blockIdx.y * BM;
    const int bn   = blockIdx.x * BN;

    const float4* Ag = (const float4*)(A + (size_t)bm * K_TOT);
    const float4* Bg = (const float4*)(B + (size_t)bn * K_TOT);

    // per-lane LDSM byte offsets (8-lane groups -> one 8x4-float matrix)
    const uint32_t laneA = ((((lane >> 3) & 1) * 8 + (lane & 7)) * ROWF
                            + ((lane >> 4) * 4)) * 4u;
    const uint32_t laneB = (((lane >> 4) * 8 + (lane & 7)) * ROWF
                            + (((lane >> 3) & 1) * 4)) * 4u;

    auto issue = [&](int c, int s) {
        const uint32_t sa  = sb + (uint32_t)(s * STG_F) * 4u;
        const uint32_t sbB = sa + (uint32_t)B_OFF * 4u;
        #pragma unroll
        for (int i = 0; i < 4; i++) {
            int f = tid + i * NTH, m = f >> 3, q = f & 7;
            cp16(sa + (uint32_t)(m * ROWF + q * 4) * 4u,
                 Ag + (size_t)m * (K_TOT / 4) + c * 8 + q);
        }
        #pragma unroll
        for (int i = 0; i < 4; i++) {
            int f = tid + i * NTH, n = f >> 3, q = f & 7;
            cp16(sbB + (uint32_t)(n * ROWF + q * 4) * 4u,
                 Bg + (size_t)n * (K_TOT / 4) + c * 8 + q);
        }
        asm volatile("cp.async.commit_group;" ::: "memory");
    };

    float acc[4][4][4];
    #pragma unroll
    for (int a = 0; a < 4; a++)
        #pragma unroll
        for (int b = 0; b < 4; b++)
            #pragma unroll
            for (int r = 0; r < 4; r++) acc[a][b][r] = 0.0f;

    issue(0, 0);
    issue(1, 1);

    const uint32_t kstag = (uint32_t)(wid & 3);

    for (int c = 0; c < NCH; c++) {
        asm volatile("cp.async.wait_group 1;" ::: "memory");
        __syncthreads();
        if (c + 2 < NCH) issue(c + 2, (c + 2) % NSTAGE);
        else asm volatile("cp.async.commit_group;" ::: "memory");

        const uint32_t sA = sb + (uint32_t)((c % NSTAGE) * STG_F) * 4u;
        const uint32_t sB = sA + (uint32_t)B_OFF * 4u;
        const uint32_t aBase = sA + (uint32_t)(wm * 64 * ROWF) * 4u + laneA;
        const uint32_t bBase = sB + (uint32_t)(wn * 32 * ROWF) * 4u + laneB;

        #pragma unroll
        for (int kk = 0; kk < 4; kk++) {
            const uint32_t kbb = ((kk + kstag) & 3u) * 32u;  // k offset (bytes)
            uint32_t a[4][4], b[2][4];
            #pragma unroll
            for (int mt = 0; mt < 4; mt++)
                ldsm4(a[mt], aBase + (uint32_t)(mt * 16 * ROWF) * 4u + kbb);
            #pragma unroll
            for (int p = 0; p < 2; p++)
                ldsm4(b[p], bBase + (uint32_t)(p * 16 * ROWF) * 4u + kbb);
            if (ROUND_A) {
                #pragma unroll
                for (int mt = 0; mt < 4; mt++)
                    #pragma unroll
                    for (int j = 0; j < 4; j++)
                        a[mt][j] = f2tf(__uint_as_float(a[mt][j]));
            }
            #pragma unroll
            for (int mt = 0; mt < 4; mt++) {
                #pragma unroll
                for (int nt = 0; nt < 4; nt++) {
                    uint32_t b0 = b[nt >> 1][(nt & 1) * 2 + 0];
                    uint32_t b1 = b[nt >> 1][(nt & 1) * 2 + 1];
                    mma8(acc[mt][nt], a[mt], b0, b1);
                }
            }
        }
    }

    // ---- epilogue ----
    #pragma unroll
    for (int mt = 0; mt < 4; mt++) {
        int m = bm + wm * 64 + mt * 16 + lr;
        float* crow = C + (size_t)m * N_TOT + bn + wn * 32;
        #pragma unroll
        for (int nt = 0; nt < 4; nt++) {
            int nf = nt * 8 + lc * 2;
            *(float2*)(crow + nf) = make_float2(acc[mt][nt][0], acc[mt][nt][1]);
            *(float2*)(crow + nf + (size_t)8 * N_TOT) =
                make_float2(acc[mt][nt][2], acc[mt][nt][3]);
        }
    }
}

// ---------------- tf32 (rna) pre-round, vectorized (weights only) ------------
__global__ void round_kernel(const float4* __restrict__ w, float4* __restrict__ o)
{
    int i = blockIdx.x * 256 + threadIdx.x;
    float4 v = w[i];
    o[i] = make_float4(__uint_as_float(f2tf(v.x)), __uint_as_float(f2tf(v.y)),
                       __uint_as_float(f2tf(v.z)), __uint_as_float(f2tf(v.w)));
}

// ---- 5-tap Gaussian window, per-head shift {0,-1,+1,0}x2; output tf32-rounded
__global__ void conv_kernel(const float4* __restrict__ V, float4* __restrict__ Vc)
{
    int idx = blockIdx.x * blockDim.x + threadIdx.x;   // M_TOT*128 threads
    int c4  = idx & 127;
    int m   = idx >> 7;
    int s   = m & 4095;
    int mb0 = m - s;
    int hm  = (c4 >> 4) & 3;
    int shift = (hm == 1) ? -1 : ((hm == 2) ? 1 : 0);

    const float F[5] = {0.05399096651318806f, 0.24197072451914337f,
                        0.3989422804014327f,  0.24197072451914337f,
                        0.05399096651318806f};

    float ax = 0.f, ay = 0.f, az = 0.f, aw = 0.f;
    #pragma unroll
    for (int j = 0; j < 5; j++) {
        int ss = s + shift + j - 2;
        if (ss >= 0 && ss < 4096) {
            float4 v = V[(size_t)(mb0 + ss) * 128 + c4];
            ax += F[j] * v.x; ay += F[j] * v.y; az += F[j] * v.z; aw += F[j] * v.w;
        }
    }
    Vc[idx] = make_float4(__uint_as_float(f2tf(ax)), __uint_as_float(f2tf(ay)),
                          __uint_as_float(f2tf(az)), __uint_as_float(f2tf(aw)));
}

// ---------------- launcher ----------------
extern "C" void kernel_launch(void* const* d_in, const int* in_sizes, int n_in,
                              void* d_out, int out_size)
{
    const float* values = (const float*)d_in[0];
    const float* win    = (const float*)d_in[3];
    const float* wout   = (const float*)d_in[4];
    float*       out    = (float*)d_out;

    float *pV, *pVc, *pWa, *pWb;
    cudaGetSymbolAddress((void**)&pV,  g_V);
    cudaGetSymbolAddress((void**)&pVc, g_Vc);
    cudaGetSymbolAddress((void**)&pWa, g_Wa);
    cudaGetSymbolAddress((void**)&pWb, g_Wb);

    cudaFuncSetAttribute(gemm_lds<true>,
                         cudaFuncAttributeMaxDynamicSharedMemorySize, SMEM_BYTES);
    cudaFuncSetAttribute(gemm_lds<false>,
                         cudaFuncAttributeMaxDynamicSharedMemorySize, SMEM_BYTES);

    dim3 grid(N_TOT / BN, M_TOT / BM);   // (4, 256)

    round_kernel<<<256, 256>>>((const float4*)win,  (float4*)pWa);
    round_kernel<<<256, 256>>>((const float4*)wout, (float4*)pWb);
    gemm_lds<true ><<<grid, NTH, SMEM_BYTES>>>(values, pWa, pV);
    conv_kernel<<<(M_TOT * 128) / 256, 256>>>((const float4*)pV, (float4*)pVc);
    gemm_lds<false><<<grid, NTH, SMEM_BYTES>>>(pVc, pWb, out);
}